// round 15
// baseline (speedup 1.0000x reference)
#include <cuda_runtime.h>
#include <cuda_bf16.h>
#include <cuda_fp16.h>
#include <math.h>
#include <stdint.h>

#define T_ 512
#define B_ 256
#define D_ 256
#define H_ 256
#define Q_ 256
#define M_ (T_*B_)
#define MT 128
#define NTILES (M_/MT)
#define NCTA 152
#define EXTRA (NTILES - NCTA*6)

#if defined(__CUDA_ARCH__) && (defined(__CUDA_ARCH_FEAT_SM103_ALL) || defined(__CUDA_ARCH_FEAT_SM100_ALL) || defined(__CUDA_ARCH_FEAT_SM110_ALL) || (defined(__CUDA_ARCH_SPECIFIC__) && (__CUDA_ARCH_SPECIFIC__ == 1030 || __CUDA_ARCH_SPECIFIC__ == 1000)))
#define USE_TCGEN05 1
#else
#define USE_TCGEN05 0
#endif

#define IDESC ((1u<<4)|((256u/8)<<17)|((128u/16)<<24))

// ---- scratch ----
__device__ float g_wsum[4*256];
__device__ float g_Wt[4*256*256];                        // fp32 (fallback path)
__device__ float g_gf[4*M_];
__device__ float g_conv[M_];
__device__ __align__(1024) uint8_t g_Wb[4*2*8*16384];    // [gate][split][kc8] 16KB SW64 fp16 chunks
__device__ __align__(1024) uint8_t g_X0[(size_t)M_*D_*2]; // split x0, SW128 64KB tiles (crew-written)
__device__ __align__(1024) uint8_t g_X1[(size_t)M_*D_*2]; // split x1

// ---- smem offsets ----
#define SM_A0     0                      // 65536 : x0 SW128 tile
#define SM_A1     65536                  // 65536 : x1 SW128 tile
#define SM_W      131072                 // 5 x 16384 weight ring
#define SM_THR    213504                 // 4*256 floats (0.5 - bias)
#define SM_WS2    217600                 // 4*256 floats (wsum)
#define SM_TPTR   221696
#define SM_BAR    221712
#define SMEM_DYN  223232

#define BAR_FULL(s)  (sb + SM_BAR + (s)*8)        // 5 slots
#define BAR_EMPTY(s) (sb + SM_BAR + 40 + (s)*8)   // 5 slots
#define BAR_EPI      (sb + SM_BAR + 80)
#define BAR_DFREE(b) (sb + SM_BAR + 88 + (b)*8)   // 2 buffers
#define BAR_X        (sb + SM_BAR + 104)
#define BAR_XFREE    (sb + SM_BAR + 112)
#define BAR_XS(s)    (sb + SM_BAR + 120 + (s)*8)  // 2 slots, crew -> producer
#define BAR_TOK(s)   (sb + SM_BAR + 136 + (s)*8)  // 2 slots, producer -> crew

// ============================ common helpers ============================
__device__ __forceinline__ uint32_t smem_u32(const void* p){
    uint32_t a;
    asm("{ .reg .u64 t; cvta.to.shared.u64 t, %1; cvt.u32.u64 %0, t; }" : "=r"(a) : "l"(p));
    return a;
}
__device__ __forceinline__ void split2h(float v, __half& s0, __half& s1){
    s0 = __float2half_rn(v);
    s1 = __float2half_rn(v - __half2float(s0));
}
__device__ __forceinline__ uint32_t sw128_tile_off(int r, int c){
    uint32_t off = (uint32_t)(((r>>3) + (c>>6)*16)*1024 + (r&7)*128 + (c&63)*2);
    return off ^ ((off>>3) & 0x70);
}

#if USE_TCGEN05
// ============================ tcgen05 PTX helpers ============================
__device__ __forceinline__ uint32_t elect_one(){
    uint32_t p;
    asm volatile("{\n\t.reg .pred p;\n\telect.sync _|p, 0xFFFFFFFF;\n\tselp.b32 %0,1,0,p;\n\t}":"=r"(p));
    return p;
}
__device__ __forceinline__ uint32_t cluster_rank(){
    uint32_t r; asm("mov.u32 %0, %%cluster_ctarank;" : "=r"(r)); return r;
}
#define MBAR_INIT(a,c) asm volatile("mbarrier.init.shared.b64 [%0], %1;"::"r"(a),"r"(c):"memory")
#define MBAR_INVAL(a)  asm volatile("mbarrier.inval.shared.b64 [%0];"::"r"(a):"memory")
#define MBAR_ARRIVE(a) asm volatile("mbarrier.arrive.shared.b64 _, [%0];"::"r"(a):"memory")
#define MBAR_WAIT(a,ph) do{ uint32_t _m=(a),_p=(ph),_d; \
    asm volatile("{\n\t.reg .pred p;\n\tmbarrier.try_wait.parity.acquire.cta.shared::cta.b64 p,[%1],%2;\n\tselp.b32 %0,1,0,p;\n\t}":"=r"(_d):"r"(_m),"r"(_p):"memory"); \
    if(!_d){ asm volatile("{\n\t.reg .pred P1;\n\tWL_%=:\n\tmbarrier.try_wait.parity.acquire.cta.shared::cta.b64 P1,[%0],%1,0x989680;\n\t@P1 bra.uni WD_%=;\n\tbra.uni WL_%=;\n\tWD_%=:\n\t}"::"r"(_m),"r"(_p):"memory"); } }while(0)
#define MBAR_EXPECT_TX(a,n) asm volatile("mbarrier.arrive.expect_tx.shared.b64 _, [%0], %1;"::"r"(a),"r"(n):"memory")

#define TC_ALLOC(sa,n)   asm volatile("tcgen05.alloc.cta_group::1.sync.aligned.shared::cta.b32 [%0], %1;"::"r"(sa),"r"(n):"memory")
#define TC_DEALLOC(t,n)  asm volatile("tcgen05.dealloc.cta_group::1.sync.aligned.b32 %0, %1;"::"r"(t),"r"(n))
#define TC_COMMIT(a)     asm volatile("tcgen05.commit.cta_group::1.mbarrier::arrive::one.shared::cluster.b64 [%0];"::"r"(a):"memory")
#define TC_COMMIT_MC(a,mask) asm volatile("tcgen05.commit.cta_group::1.mbarrier::arrive::one.shared::cluster.multicast::cluster.b64 [%0], %1;"::"r"(a),"h"((uint16_t)(mask)):"memory")
#define TC_FENCE_AFTER()  asm volatile("tcgen05.fence::after_thread_sync;":::"memory")
#define TC_FENCE_BEFORE() asm volatile("tcgen05.fence::before_thread_sync;":::"memory")
#define TC_WAIT_LD()     asm volatile("tcgen05.wait::ld.sync.aligned;":::"memory")
#define CLUSTER_ARRIVE() asm volatile("barrier.cluster.arrive.aligned;" ::: "memory")
#define CLUSTER_WAIT()   asm volatile("barrier.cluster.wait.aligned;" ::: "memory")

#define TC_LD_X32(r, a) \
    asm volatile("tcgen05.ld.sync.aligned.32x32b.x32.b32 " \
        "{%0,%1,%2,%3,%4,%5,%6,%7,%8,%9,%10,%11,%12,%13,%14,%15," \
        "%16,%17,%18,%19,%20,%21,%22,%23,%24,%25,%26,%27,%28,%29,%30,%31}, [%32];" \
        : "=r"((r)[0]),"=r"((r)[1]),"=r"((r)[2]),"=r"((r)[3]),"=r"((r)[4]),"=r"((r)[5]),"=r"((r)[6]),"=r"((r)[7]), \
          "=r"((r)[8]),"=r"((r)[9]),"=r"((r)[10]),"=r"((r)[11]),"=r"((r)[12]),"=r"((r)[13]),"=r"((r)[14]),"=r"((r)[15]), \
          "=r"((r)[16]),"=r"((r)[17]),"=r"((r)[18]),"=r"((r)[19]),"=r"((r)[20]),"=r"((r)[21]),"=r"((r)[22]),"=r"((r)[23]), \
          "=r"((r)[24]),"=r"((r)[25]),"=r"((r)[26]),"=r"((r)[27]),"=r"((r)[28]),"=r"((r)[29]),"=r"((r)[30]),"=r"((r)[31]) \
        : "r"(a))

static constexpr uint64_t DESC_BASE_SW128 =
    (uint64_t(2)<<61) | (uint64_t(1)<<46) | (uint64_t(64)<<32) | (uint64_t(1)<<16);
static constexpr uint64_t DESC_BASE_SW64 =
    (uint64_t(4)<<61) | (uint64_t(1)<<46) | (uint64_t(32)<<32) | (uint64_t(1)<<16);
__device__ __forceinline__ uint64_t make_desc(uint32_t addr){
    return DESC_BASE_SW128 | (uint64_t)((addr>>4)&0x3FFF);
}
__device__ __forceinline__ uint64_t make_desc64(uint32_t addr){
    return DESC_BASE_SW64 | (uint64_t)((addr>>4)&0x3FFF);
}
__device__ __forceinline__ void mma_ss(uint32_t d, uint64_t a, uint64_t b, uint32_t en){
    asm volatile("{\n\t.reg .pred p;\n\tsetp.ne.u32 p, %4, 0;\n\t"
        "tcgen05.mma.cta_group::1.kind::f16 [%0], %1, %2, %3, {%5,%5,%5,%5}, p;\n\t}"
        :: "r"(d), "l"(a), "l"(b), "r"(IDESC), "r"(en), "r"(0u) : "memory");
}
__device__ __forceinline__ void bulk_ldn(uint32_t dst, const void* src, uint32_t n, uint32_t mbar){
    asm volatile("{\n\t.reg .u64 g;\n\tcvta.to.global.u64 g, %1;\n\t"
        "cp.async.bulk.shared::cluster.global.mbarrier::complete_tx::bytes [%0], [g], %2, [%3];\n\t}"
        :: "r"(dst), "l"(src), "r"(n), "r"(mbar) : "memory");
}
__device__ __forceinline__ void bulk_ldn_mc(uint32_t dst, const void* src, uint32_t n, uint32_t mbar, uint16_t mask){
    asm volatile("{\n\t.reg .u64 g;\n\tcvta.to.global.u64 g, %1;\n\t"
        "cp.async.bulk.shared::cluster.global.mbarrier::complete_tx::bytes.multicast::cluster [%0], [g], %2, [%3], %4;\n\t}"
        :: "r"(dst), "l"(src), "r"(n), "r"(mbar), "h"(mask) : "memory");
}
#endif // USE_TCGEN05

// ============================ K0: weight prep only ============================
__global__ __launch_bounds__(256) void prep_kernel(
    const float* __restrict__ Wf, const float* __restrict__ Wi,
    const float* __restrict__ Wu, const float* __restrict__ Wo)
{
    __shared__ float red[256];
    int g = blockIdx.x >> 8;
    int q = blockIdx.x & 255;
    int k = threadIdx.x;
    const float* W = (g==0)?Wf:(g==1)?Wi:(g==2)?Wu:Wo;

    float w = W[q*512 + k];
    g_Wt[(g*256 + k)*256 + q] = w;                   // fp32 for fallback

    __half w0, w1; split2h(w, w0, w1);
    uint32_t off = (uint32_t)((q>>3)*512 + (q&7)*64 + (k&31)*2);
    off ^= (off>>3) & 0x30;                          // SW64 swizzle
    int kc8 = k >> 5;
    *(__half*)(g_Wb + ((size_t)((g*2+0)*8 + kc8))*16384 + off) = w0;
    *(__half*)(g_Wb + ((size_t)((g*2+1)*8 + kc8))*16384 + off) = w1;

    red[k] = W[q*512 + 256 + k];
    __syncthreads();
    for (int s = 128; s > 0; s >>= 1) {
        if (k < s) red[k] += red[k+s];
        __syncthreads();
    }
    if (k == 0) g_wsum[g*256 + q] = red[0];
}

// ============================ K1: persistent GEMM + in-kernel pipelined xsplit ============================
__global__ __launch_bounds__(256, 1) __cluster_dims__(2, 1, 1) void qmma_kernel(
    const float* __restrict__ x,
    const float* __restrict__ bfp, const float* __restrict__ bip,
    const float* __restrict__ bup, const float* __restrict__ bop)
{
    extern __shared__ uint8_t smem_raw[];
    const int tid = threadIdx.x;
    const int ci  = blockIdx.x;
    const int iters = 6 + (ci < EXTRA ? 1 : 0);

#if USE_TCGEN05
    uint32_t sraw = smem_u32(smem_raw);
    uint32_t sb   = (sraw + 1023u) & ~1023u;
    uint8_t* sm   = smem_raw + (sb - sraw);
    const int wid = tid >> 5;
    const int lane = tid & 31;
    const uint32_t rank = cluster_rank();

    if (wid == 0) TC_ALLOC(sb + SM_TPTR, 512);
    if (tid == 0) {
#pragma unroll
        for (int s = 0; s < 5; s++) { MBAR_INIT(BAR_FULL(s),1); MBAR_INIT(BAR_EMPTY(s),2); }
        MBAR_INIT(BAR_EPI,1);
        MBAR_INIT(BAR_DFREE(0),1); MBAR_INIT(BAR_DFREE(1),1);
        MBAR_INIT(BAR_X,1);
        MBAR_INIT(BAR_XFREE,1);
        MBAR_INIT(BAR_XS(0),64);  MBAR_INIT(BAR_XS(1),64);   // crew: 2 warps x 32
        MBAR_INIT(BAR_TOK(0),1);  MBAR_INIT(BAR_TOK(1),1);
    }
    __syncthreads();
    uint32_t tmem;
    asm volatile("ld.shared.b32 %0, [%1];" : "=r"(tmem) : "r"(sb + SM_TPTR));

    // ---- one-time prologue: tables; arm 5 W slots (A TMAs now live in producer loop) ----
    if (tid == 0) {
#pragma unroll
        for (int s = 0; s < 5; s++) MBAR_EXPECT_TX(BAR_FULL(s), 16384u);
    }
#pragma unroll
    for (int i = 0; i < 4; i++) {
        int idx = tid + i*256;
        int g2 = idx >> 8, q = idx & 255;
        const float* bg = (g2==0)?bfp:(g2==1)?bip:(g2==2)?bup:bop;
        ((float*)(sm + SM_THR))[idx] = 0.5f - bg[q];
        ((float*)(sm + SM_WS2))[idx] = g_wsum[idx];
    }
    __syncthreads();
    CLUSTER_ARRIVE(); CLUSTER_WAIT();

    if (wid == 1 || wid == 3) {
        // -------- split crew: x (fp32) -> g_X0/g_X1/g_conv for this CTA's tiles --------
        const int cw = (wid == 3);     // 0 or 1: which 64-row half
        for (int it = 0; it < iters; it++) {
            if (it >= 2) MBAR_WAIT(BAR_TOK(it & 1), ((it - 2) >> 1) & 1);   // depth-2 token
            const int tile = it*NCTA + ci;
            const size_t base = (size_t)tile * 65536;
#pragma unroll 2
            for (int jj = 0; jj < 64; jj++) {
                const int r   = cw*64 + jj;
                const int row = tile*128 + r;

                const float4* xr = (const float4*)(x + (size_t)row * D_ + lane * 8);
                float4 v0 = xr[0], v1 = xr[1];
                float e[8] = {v0.x, v0.y, v0.z, v0.w, v1.x, v1.y, v1.z, v1.w};

                unsigned b = 0;
#pragma unroll
                for (int i = 0; i < 8; i++) b |= (e[i] > 0.0f) ? (1u << i) : 0u;
                unsigned p = b;
                p = (p ^ (p << 1)) & 0xFFu;
                p = (p ^ (p << 2)) & 0xFFu;
                p = (p ^ (p << 4)) & 0xFFu;
                unsigned lane_par = __popc(b) & 1u;
                unsigned mask = __ballot_sync(0xFFFFFFFFu, lane_par);
                unsigned pre  = __popc(mask & ((1u << lane) - 1u)) & 1u;
                int cnt = __popc((p ^ (pre ? 0xFFu : 0u)) & 0xFFu);
                cnt = __reduce_add_sync(0xFFFFFFFFu, cnt);
                if (lane == 0) g_conv[row] = (float)cnt * (1.0f/256.0f);

                uint32_t h0p[4], h1p[4];
#pragma unroll
                for (int k = 0; k < 4; k++) {
                    float e0 = e[2*k], e1 = e[2*k+1];
                    __half2 h0 = __floats2half2_rn(e0, e1);
                    float r0 = e0 - __low2float(h0);
                    float r1 = e1 - __high2float(h0);
                    __half2 h1 = __floats2half2_rn(r0, r1);
                    h0p[k] = *(uint32_t*)&h0;
                    h1p[k] = *(uint32_t*)&h1;
                }
                uint32_t sw = sw128_tile_off(r, lane * 8);
                *(uint4*)(g_X0 + base + sw) = make_uint4(h0p[0], h0p[1], h0p[2], h0p[3]);
                *(uint4*)(g_X1 + base + sw) = make_uint4(h1p[0], h1p[1], h1p[2], h1p[3]);
            }
            __threadfence();                 // STGs visible before producer's TMA reads
            MBAR_ARRIVE(BAR_XS(it & 1));     // all 64 crew threads arrive
        }
    } else if (wid == 2) {
        if (lane == 0) {
            // -------- producer: xs-gated A TMAs + continuous W chunk stream --------
            int cc = (int)rank;
            for (int it = 0; it < iters; it++) {
                MBAR_WAIT(BAR_XS(it & 1), (it >> 1) & 1);        // crew done with tile it
                if (it > 0) MBAR_WAIT(BAR_XFREE, (it-1)&1);      // smem A free
                MBAR_EXPECT_TX(BAR_X, 131072u);
                size_t tb = (size_t)(it*NCTA + ci) * 65536;
                bulk_ldn(sb + SM_A0, g_X0 + tb, 65536u, BAR_X);
                bulk_ldn(sb + SM_A1, g_X1 + tb, 65536u, BAR_X);
                MBAR_ARRIVE(BAR_TOK(it & 1));                    // release crew token
                int lim = (it+1)*64;
                while (cc < lim) {
                    int k = cc / 5, slot = cc - k*5;
                    if (k > 0) MBAR_WAIT(BAR_EMPTY(slot), (k-1)&1);
                    int c2 = cc & 63;
                    int g = c2 >> 4, idx = c2 & 15, s = idx >> 3, kc8 = idx & 7;
                    bulk_ldn_mc(sb + SM_W + slot*16384,
                                g_Wb + ((size_t)((g*2+s)*8 + kc8))*16384,
                                16384u, BAR_FULL(slot), 0x3);
                    cc += 2;
                }
            }
        }
    } else if (wid == 0) {
        if (elect_one()) {
            // -------- MMA issuer (continuous across tiles) --------
            const uint64_t a0d = make_desc(sb + SM_A0);
            const uint64_t a1d = make_desc(sb + SM_A1);
            int sl = 0, ku = 0, dfp0 = 0, dfp1 = 0, ggc = 0, gchunk = 0;
            const int tot = 64 * iters;
            for (int it = 0; it < iters; it++) {
                MBAR_WAIT(BAR_X, it & 1);
                TC_FENCE_AFTER();
                uint32_t en = 0;
                for (int c2 = 0; c2 < 64; c2++) {
                    MBAR_WAIT(BAR_FULL(sl), ku);
                    int idx = c2 & 15, s = idx >> 3, kc8 = idx & 7;
                    if (idx == 0) {
                        if (ggc >= 2) {
                            if ((ggc & 1) == 0) { MBAR_WAIT(BAR_DFREE(0), dfp0); dfp0 ^= 1; }
                            else                { MBAR_WAIT(BAR_DFREE(1), dfp1); dfp1 ^= 1; }
                            TC_FENCE_AFTER();
                        }
                        en = 0;
                    }
                    uint32_t dT = tmem + (uint32_t)(ggc & 1) * 256;
                    uint64_t bd = make_desc64(sb + SM_W + sl*16384);
                    uint64_t aoff = (uint64_t)((kc8>>1)*1024 + (kc8&1)*4);
                    mma_ss(dT, a0d + aoff,     bd,     en); en = 1;
                    mma_ss(dT, a0d + aoff + 2, bd + 2, 1);
                    if (s == 0) {
                        mma_ss(dT, a1d + aoff,     bd,     1);
                        mma_ss(dT, a1d + aoff + 2, bd + 2, 1);
                    }
                    if (gchunk + 5 < tot) MBAR_EXPECT_TX(BAR_FULL(sl), 16384u);
                    TC_COMMIT_MC(BAR_EMPTY(sl), 0x3);
                    if (idx == 15) { TC_COMMIT(BAR_EPI); ggc++; }
                    if (++sl == 5) { sl = 0; ku ^= 1; }
                    gchunk++;
                }
                TC_COMMIT(BAR_XFREE);   // fires when this tile's MMAs complete -> A refill safe
            }
        }
    } else {
        // -------- epilogue (wid >= 4): continuous D ping-pong across tiles --------
        const int row = tid - 128;
        int ep = 0;
        const int ngg = 4 * iters;
        for (int gg = 0; gg < ngg; gg++) {
            MBAR_WAIT(BAR_EPI, ep); ep ^= 1;
            TC_FENCE_AFTER();
            const int it = gg >> 2, g = gg & 3;
            const int m0 = (it*NCTA + ci) * MT;
            const float cv = g_conv[m0 + row];
            const uint32_t dT = tmem + (uint32_t)(gg & 1) * 256;
            const float* thr0 = (const float*)(sm + SM_THR) + g*256;
            const float* ws   = (const float*)(sm + SM_WS2) + g*256;
            int par = 0, cnt = 0;
            uint32_t rA[32], rB[32];
            TC_LD_X32(rA, dT);
#pragma unroll
            for (int cc = 0; cc < 8; cc += 2) {
                TC_WAIT_LD();
                TC_LD_X32(rB, dT + (cc+1)*32);
                {
                    uint32_t word = 0;
#pragma unroll
                    for (int jj = 0; jj < 32; jj++) {
                        float thr = fmaf(-cv, ws[cc*32+jj], thr0[cc*32+jj]);
                        if (__uint_as_float(rA[jj]) > thr) word |= (1u << jj);
                    }
                    uint32_t p = word;
                    p ^= p << 1; p ^= p << 2; p ^= p << 4; p ^= p << 8; p ^= p << 16;
                    cnt += __popc(p ^ (par ? 0xFFFFFFFFu : 0u));
                    par ^= (int)(p >> 31);
                }
                TC_WAIT_LD();
                if (cc + 2 < 8) TC_LD_X32(rA, dT + (cc+2)*32);
                {
                    uint32_t word = 0;
#pragma unroll
                    for (int jj = 0; jj < 32; jj++) {
                        float thr = fmaf(-cv, ws[(cc+1)*32+jj], thr0[(cc+1)*32+jj]);
                        if (__uint_as_float(rB[jj]) > thr) word |= (1u << jj);
                    }
                    uint32_t p = word;
                    p ^= p << 1; p ^= p << 2; p ^= p << 4; p ^= p << 8; p ^= p << 16;
                    cnt += __popc(p ^ (par ? 0xFFFFFFFFu : 0u));
                    par ^= (int)(p >> 31);
                }
            }
            g_gf[g*M_ + m0 + row] = (float)cnt * (1.0f/256.0f);
            TC_FENCE_BEFORE();
            asm volatile("bar.sync 1, 128;" ::: "memory");
            if (tid == 128) MBAR_ARRIVE(BAR_DFREE(gg & 1));
        }
    }

    __syncthreads();
    if (tid == 0) {
#pragma unroll
        for (int s = 0; s < 5; s++) { MBAR_INVAL(BAR_FULL(s)); MBAR_INVAL(BAR_EMPTY(s)); }
        MBAR_INVAL(BAR_EPI);
        MBAR_INVAL(BAR_DFREE(0)); MBAR_INVAL(BAR_DFREE(1));
        MBAR_INVAL(BAR_X); MBAR_INVAL(BAR_XFREE);
        MBAR_INVAL(BAR_XS(0)); MBAR_INVAL(BAR_XS(1));
        MBAR_INVAL(BAR_TOK(0)); MBAR_INVAL(BAR_TOK(1));
    }
    __syncthreads();
    if (wid == 0) TC_DEALLOC(tmem, 512);
    CLUSTER_ARRIVE(); CLUSTER_WAIT();

#else  // ======================= fp32 fallback (compute_103 pass) =======================
    float* xs    = (float*)smem_raw;                 // 128 x 260
    float* ws    = (float*)(smem_raw + 133120);      // 32 x 256
    float* convs = (float*)(smem_raw + 165888);      // 128
    unsigned char* bits = smem_raw + 166400;         // 64 x 264

    for (int it = 0; it < iters; it++) {
        const int m0 = (it*NCTA + ci) * MT;
        const float4* xblk = (const float4*)(x + (size_t)m0 * D_);
#pragma unroll 4
        for (int i = 0; i < 32; i++) {
            int idx = tid + i*256;
            int r = idx >> 6, c = idx & 63;
            *(float4*)(xs + r*260 + c*4) = xblk[idx];
        }
        __syncthreads();

        if (tid < 128) {
            const float* xrow = xs + tid*260;
            int par = 0, cnt = 0;
#pragma unroll 8
            for (int q = 0; q < D_; q++) { par ^= (xrow[q] > 0.0f); cnt += par; }
            convs[tid] = (float)cnt * (1.0f/256.0f);
        }
        __syncthreads();

        const int rowg = tid >> 4;
        const int colg = tid & 15;
        const int r0   = rowg * 4;

        for (int g = 0; g < 4; g++) {
            const float* bias = (g==0)?bfp:(g==1)?bip:(g==2)?bup:bop;
            const float* wsum = g_wsum + g*256;

            for (int rh = 0; rh < 2; rh++) {
                float acc[4][16];
#pragma unroll
                for (int i = 0; i < 4; i++)
#pragma unroll
                    for (int j = 0; j < 16; j++) acc[i][j] = 0.0f;

                for (int ks = 0; ks < 8; ks++) {
                    float4* d = (float4*)ws;
                    const float4* s = (const float4*)(g_Wt + g*65536 + ks*8192);
#pragma unroll
                    for (int i = 0; i < 8; i++) d[tid + i*256] = s[tid + i*256];
                    __syncthreads();
                    const float* xk = xs + (rh*64 + r0)*260 + ks*32;
#pragma unroll 4
                    for (int kk = 0; kk < 32; kk++) {
                        float x0 = xk[0*260 + kk];
                        float x1 = xk[1*260 + kk];
                        float x2 = xk[2*260 + kk];
                        float x3 = xk[3*260 + kk];
                        const float* wk = ws + kk*256 + colg;
#pragma unroll
                        for (int j = 0; j < 16; j++) {
                            float wv = wk[j*16];
                            acc[0][j] = fmaf(x0, wv, acc[0][j]);
                            acc[1][j] = fmaf(x1, wv, acc[1][j]);
                            acc[2][j] = fmaf(x2, wv, acc[2][j]);
                            acc[3][j] = fmaf(x3, wv, acc[3][j]);
                        }
                    }
                    __syncthreads();
                }

                float cv0 = convs[rh*64 + r0 + 0];
                float cv1 = convs[rh*64 + r0 + 1];
                float cv2 = convs[rh*64 + r0 + 2];
                float cv3 = convs[rh*64 + r0 + 3];
#pragma unroll
                for (int j = 0; j < 16; j++) {
                    int q = colg + j*16;
                    float wq = wsum[q];
                    float bq = bias[q];
                    bits[(r0+0)*264 + q] = (fmaf(cv0, wq, acc[0][j] + bq) > 0.5f);
                    bits[(r0+1)*264 + q] = (fmaf(cv1, wq, acc[1][j] + bq) > 0.5f);
                    bits[(r0+2)*264 + q] = (fmaf(cv2, wq, acc[2][j] + bq) > 0.5f);
                    bits[(r0+3)*264 + q] = (fmaf(cv3, wq, acc[3][j] + bq) > 0.5f);
                }
                __syncthreads();

                if (tid < 64) {
                    const unsigned char* br = bits + tid*264;
                    int par = 0, cnt = 0;
#pragma unroll 8
                    for (int q = 0; q < Q_; q++) { par ^= br[q]; cnt += par; }
                    g_gf[g*M_ + m0 + rh*64 + tid] = (float)cnt * (1.0f/256.0f);
                }
                __syncthreads();
            }
        }
    }
#endif
}

// ============================ K2: fused scan + output broadcast ============================
__global__ __launch_bounds__(256) void scan_out_kernel(const float* __restrict__ cx0,
                                                       float4* __restrict__ out)
{
    __shared__ float wA[8], wB[8];
    __shared__ float eA[8], eB[8];
    __shared__ float shx[T_];
    __shared__ float stail[2];

    const int b    = blockIdx.x;
    const int tid  = threadIdx.x;
    const int lane = tid & 31;
    const int wrp  = tid >> 5;

    const int t0 = tid * 2, t1 = t0 + 1;
    const int m0 = t0 * B_ + b, m1 = t1 * B_ + b;

    float a0 = 1.0f / (1.0f + expf(-g_gf[m0]));
    float i0 = 1.0f / (1.0f + expf(-g_gf[M_ + m0]));
    float u0 = tanhf(g_gf[2*M_ + m0]);
    float o0 = 1.0f / (1.0f + expf(-g_gf[3*M_ + m0]));
    float b0v = i0 * u0;

    float a1 = 1.0f / (1.0f + expf(-g_gf[m1]));
    float i1 = 1.0f / (1.0f + expf(-g_gf[M_ + m1]));
    float u1 = tanhf(g_gf[2*M_ + m1]);
    float o1 = 1.0f / (1.0f + expf(-g_gf[3*M_ + m1]));
    float b1v = i1 * u1;

    float A  = a1 * a0;
    float Bv = fmaf(a1, b0v, b1v);

#pragma unroll
    for (int off = 1; off < 32; off <<= 1) {
        float Au = __shfl_up_sync(0xFFFFFFFFu, A,  off);
        float Bu = __shfl_up_sync(0xFFFFFFFFu, Bv, off);
        if (lane >= off) { Bv = fmaf(A, Bu, Bv); A *= Au; }
    }
    if (lane == 31) { wA[wrp] = A; wB[wrp] = Bv; }
    __syncthreads();
    if (tid == 0) {
        float pA = 1.0f, pB = 0.0f;
#pragma unroll
        for (int w = 0; w < 8; w++) {
            eA[w] = pA; eB[w] = pB;
            float nA = wA[w] * pA;
            float nB = fmaf(wA[w], pB, wB[w]);
            pA = nA; pB = nB;
        }
    }
    __syncthreads();

    float FA = A * eA[wrp];
    float FB = fmaf(A, eB[wrp], Bv);
    float XA = __shfl_up_sync(0xFFFFFFFFu, FA, 1);
    float XB = __shfl_up_sync(0xFFFFFFFFu, FB, 1);
    if (lane == 0) { XA = eA[wrp]; XB = eB[wrp]; }

    float c0  = cx0[b * H_];
    float cin = fmaf(XA, c0, XB);
    float cxa = fmaf(a0, cin, b0v);
    float cxb = fmaf(a1, cxa, b1v);

    shx[t0] = o0 * tanhf(cxa);
    float hx1 = o1 * tanhf(cxb);
    shx[t1] = hx1;
    if (t1 == T_ - 1) { stail[0] = hx1; stail[1] = cxb; }
    __syncthreads();

#pragma unroll 4
    for (int i = 0; i < 128; i++) {
        int flat = i * 256 + tid;
        int t = flat >> 6, c = flat & 63;
        float v = shx[t];
        __stcs(&out[((size_t)t * B_ + b) * 64 + c], make_float4(v, v, v, v));
    }
    const unsigned OUTS_F4 = (unsigned)T_ * B_ * (H_/4);
    if (tid < 64) {
        float v = stail[0];
        __stcs(&out[OUTS_F4 + (unsigned)b * 64 + tid], make_float4(v, v, v, v));
        float v2 = stail[1];
        __stcs(&out[OUTS_F4 + (unsigned)(B_ * (H_/4)) + (unsigned)b * 64 + tid], make_float4(v2, v2, v2, v2));
    }
}

// ============================ launch ============================
extern "C" void kernel_launch(void* const* d_in, const int* in_sizes, int n_in,
                              void* d_out, int out_size)
{
    const float* x   = (const float*)d_in[0];
    const float* cx0 = (const float*)d_in[2];
    const float* Wf  = (const float*)d_in[3];
    const float* bf_ = (const float*)d_in[4];
    const float* Wi  = (const float*)d_in[5];
    const float* bi_ = (const float*)d_in[6];
    const float* Wu  = (const float*)d_in[7];
    const float* bu_ = (const float*)d_in[8];
    const float* Wo  = (const float*)d_in[9];
    const float* bo_ = (const float*)d_in[10];

    cudaFuncSetAttribute(qmma_kernel, cudaFuncAttributeMaxDynamicSharedMemorySize, SMEM_DYN);

    prep_kernel<<<1024, 256>>>(Wf, Wi, Wu, Wo);
    qmma_kernel<<<NCTA, 256, SMEM_DYN>>>(x, bf_, bi_, bu_, bo_);
    scan_out_kernel<<<B_, 256>>>(cx0, (float4*)d_out);
}

// round 16
// speedup vs baseline: 1.7579x; 1.7579x over previous
#include <cuda_runtime.h>
#include <cuda_bf16.h>
#include <cuda_fp16.h>
#include <math.h>
#include <stdint.h>

#define T_ 512
#define B_ 256
#define D_ 256
#define H_ 256
#define Q_ 256
#define M_ (T_*B_)
#define MT 128
#define NTILES (M_/MT)
#define NCTA 152
#define EXTRA (NTILES - NCTA*6)

#if defined(__CUDA_ARCH__) && (defined(__CUDA_ARCH_FEAT_SM103_ALL) || defined(__CUDA_ARCH_FEAT_SM100_ALL) || defined(__CUDA_ARCH_FEAT_SM110_ALL) || (defined(__CUDA_ARCH_SPECIFIC__) && (__CUDA_ARCH_SPECIFIC__ == 1030 || __CUDA_ARCH_SPECIFIC__ == 1000)))
#define USE_TCGEN05 1
#else
#define USE_TCGEN05 0
#endif

#define IDESC ((1u<<4)|((256u/8)<<17)|((128u/16)<<24))

// ---- scratch ----
__device__ float g_wsum[4*256];
__device__ float g_Wt[4*256*256];                        // fp32 (fallback path)
__device__ float g_gf[4*M_];
__device__ float g_conv[M_];
__device__ __align__(1024) uint8_t g_Wb[4*2*8*16384];    // [gate][split][kc8] 16KB SW64 fp16 chunks
__device__ __align__(1024) uint8_t g_X0[(size_t)M_*D_*2]; // pre-split x0, SW128 64KB tiles
__device__ __align__(1024) uint8_t g_X1[(size_t)M_*D_*2]; // pre-split x1, SW128 64KB tiles

// ---- smem offsets ----
#define SM_A0     0                      // 65536 : x0 SW128 tile
#define SM_A1     65536                  // 65536 : x1 SW128 tile
#define SM_W      131072                 // 5 x 16384 weight ring
#define SM_THR    213504                 // 4*256 floats (0.5 - bias)
#define SM_WS2    217600                 // 4*256 floats (wsum)
#define SM_TPTR   221696
#define SM_BAR    221712
#define SMEM_DYN  223232

#define BAR_FULL(s)  (sb + SM_BAR + (s)*8)        // 5 slots
#define BAR_EMPTY(s) (sb + SM_BAR + 40 + (s)*8)   // 5 slots
#define BAR_EPI      (sb + SM_BAR + 80)
#define BAR_DFREE(b) (sb + SM_BAR + 88 + (b)*8)   // 2 buffers
#define BAR_X        (sb + SM_BAR + 104)
#define BAR_XFREE    (sb + SM_BAR + 112)

// ============================ common helpers ============================
__device__ __forceinline__ uint32_t smem_u32(const void* p){
    uint32_t a;
    asm("{ .reg .u64 t; cvta.to.shared.u64 t, %1; cvt.u32.u64 %0, t; }" : "=r"(a) : "l"(p));
    return a;
}
__device__ __forceinline__ void split2h(float v, __half& s0, __half& s1){
    s0 = __float2half_rn(v);
    s1 = __float2half_rn(v - __half2float(s0));
}
__device__ __forceinline__ uint32_t sw128_tile_off(int r, int c){
    uint32_t off = (uint32_t)(((r>>3) + (c>>6)*16)*1024 + (r&7)*128 + (c&63)*2);
    return off ^ ((off>>3) & 0x70);
}

#if USE_TCGEN05
// ============================ tcgen05 PTX helpers ============================
__device__ __forceinline__ uint32_t elect_one(){
    uint32_t p;
    asm volatile("{\n\t.reg .pred p;\n\telect.sync _|p, 0xFFFFFFFF;\n\tselp.b32 %0,1,0,p;\n\t}":"=r"(p));
    return p;
}
__device__ __forceinline__ uint32_t cluster_rank(){
    uint32_t r; asm("mov.u32 %0, %%cluster_ctarank;" : "=r"(r)); return r;
}
#define MBAR_INIT(a,c) asm volatile("mbarrier.init.shared.b64 [%0], %1;"::"r"(a),"r"(c):"memory")
#define MBAR_INVAL(a)  asm volatile("mbarrier.inval.shared.b64 [%0];"::"r"(a):"memory")
#define MBAR_ARRIVE(a) asm volatile("mbarrier.arrive.shared.b64 _, [%0];"::"r"(a):"memory")
#define MBAR_WAIT(a,ph) do{ uint32_t _m=(a),_p=(ph),_d; \
    asm volatile("{\n\t.reg .pred p;\n\tmbarrier.try_wait.parity.acquire.cta.shared::cta.b64 p,[%1],%2;\n\tselp.b32 %0,1,0,p;\n\t}":"=r"(_d):"r"(_m),"r"(_p):"memory"); \
    if(!_d){ asm volatile("{\n\t.reg .pred P1;\n\tWL_%=:\n\tmbarrier.try_wait.parity.acquire.cta.shared::cta.b64 P1,[%0],%1,0x989680;\n\t@P1 bra.uni WD_%=;\n\tbra.uni WL_%=;\n\tWD_%=:\n\t}"::"r"(_m),"r"(_p):"memory"); } }while(0)
#define MBAR_EXPECT_TX(a,n) asm volatile("mbarrier.arrive.expect_tx.shared.b64 _, [%0], %1;"::"r"(a),"r"(n):"memory")

#define TC_ALLOC(sa,n)   asm volatile("tcgen05.alloc.cta_group::1.sync.aligned.shared::cta.b32 [%0], %1;"::"r"(sa),"r"(n):"memory")
#define TC_DEALLOC(t,n)  asm volatile("tcgen05.dealloc.cta_group::1.sync.aligned.b32 %0, %1;"::"r"(t),"r"(n))
#define TC_COMMIT(a)     asm volatile("tcgen05.commit.cta_group::1.mbarrier::arrive::one.shared::cluster.b64 [%0];"::"r"(a):"memory")
#define TC_COMMIT_MC(a,mask) asm volatile("tcgen05.commit.cta_group::1.mbarrier::arrive::one.shared::cluster.multicast::cluster.b64 [%0], %1;"::"r"(a),"h"((uint16_t)(mask)):"memory")
#define TC_FENCE_AFTER()  asm volatile("tcgen05.fence::after_thread_sync;":::"memory")
#define TC_FENCE_BEFORE() asm volatile("tcgen05.fence::before_thread_sync;":::"memory")
#define TC_WAIT_LD()     asm volatile("tcgen05.wait::ld.sync.aligned;":::"memory")
#define CLUSTER_ARRIVE() asm volatile("barrier.cluster.arrive.aligned;" ::: "memory")
#define CLUSTER_WAIT()   asm volatile("barrier.cluster.wait.aligned;" ::: "memory")

#define TC_LD_X32(r, a) \
    asm volatile("tcgen05.ld.sync.aligned.32x32b.x32.b32 " \
        "{%0,%1,%2,%3,%4,%5,%6,%7,%8,%9,%10,%11,%12,%13,%14,%15," \
        "%16,%17,%18,%19,%20,%21,%22,%23,%24,%25,%26,%27,%28,%29,%30,%31}, [%32];" \
        : "=r"((r)[0]),"=r"((r)[1]),"=r"((r)[2]),"=r"((r)[3]),"=r"((r)[4]),"=r"((r)[5]),"=r"((r)[6]),"=r"((r)[7]), \
          "=r"((r)[8]),"=r"((r)[9]),"=r"((r)[10]),"=r"((r)[11]),"=r"((r)[12]),"=r"((r)[13]),"=r"((r)[14]),"=r"((r)[15]), \
          "=r"((r)[16]),"=r"((r)[17]),"=r"((r)[18]),"=r"((r)[19]),"=r"((r)[20]),"=r"((r)[21]),"=r"((r)[22]),"=r"((r)[23]), \
          "=r"((r)[24]),"=r"((r)[25]),"=r"((r)[26]),"=r"((r)[27]),"=r"((r)[28]),"=r"((r)[29]),"=r"((r)[30]),"=r"((r)[31]) \
        : "r"(a))

static constexpr uint64_t DESC_BASE_SW128 =
    (uint64_t(2)<<61) | (uint64_t(1)<<46) | (uint64_t(64)<<32) | (uint64_t(1)<<16);
static constexpr uint64_t DESC_BASE_SW64 =
    (uint64_t(4)<<61) | (uint64_t(1)<<46) | (uint64_t(32)<<32) | (uint64_t(1)<<16);
__device__ __forceinline__ uint64_t make_desc(uint32_t addr){
    return DESC_BASE_SW128 | (uint64_t)((addr>>4)&0x3FFF);
}
__device__ __forceinline__ uint64_t make_desc64(uint32_t addr){
    return DESC_BASE_SW64 | (uint64_t)((addr>>4)&0x3FFF);
}
__device__ __forceinline__ void mma_ss(uint32_t d, uint64_t a, uint64_t b, uint32_t en){
    asm volatile("{\n\t.reg .pred p;\n\tsetp.ne.u32 p, %4, 0;\n\t"
        "tcgen05.mma.cta_group::1.kind::f16 [%0], %1, %2, %3, {%5,%5,%5,%5}, p;\n\t}"
        :: "r"(d), "l"(a), "l"(b), "r"(IDESC), "r"(en), "r"(0u) : "memory");
}
__device__ __forceinline__ void bulk_ldn(uint32_t dst, const void* src, uint32_t n, uint32_t mbar){
    asm volatile("{\n\t.reg .u64 g;\n\tcvta.to.global.u64 g, %1;\n\t"
        "cp.async.bulk.shared::cluster.global.mbarrier::complete_tx::bytes [%0], [g], %2, [%3];\n\t}"
        :: "r"(dst), "l"(src), "r"(n), "r"(mbar) : "memory");
}
__device__ __forceinline__ void bulk_ldn_mc(uint32_t dst, const void* src, uint32_t n, uint32_t mbar, uint16_t mask){
    asm volatile("{\n\t.reg .u64 g;\n\tcvta.to.global.u64 g, %1;\n\t"
        "cp.async.bulk.shared::cluster.global.mbarrier::complete_tx::bytes.multicast::cluster [%0], [g], %2, [%3], %4;\n\t}"
        :: "r"(dst), "l"(src), "r"(n), "r"(mbar), "h"(mask) : "memory");
}
#endif // USE_TCGEN05

// ============================ K0: fused weight prep + x split/conv ============================
__global__ __launch_bounds__(256) void prep_xsplit_kernel(
    const float* __restrict__ x,
    const float* __restrict__ Wf, const float* __restrict__ Wi,
    const float* __restrict__ Wu, const float* __restrict__ Wo)
{
    __shared__ float red[256];

    if (blockIdx.x < 1024) {
        // ---- weight prep: SW64 16KB chunks [gate][split][kc8] (256 q x 32 k) ----
        int g = blockIdx.x >> 8;
        int q = blockIdx.x & 255;
        int k = threadIdx.x;
        const float* W = (g==0)?Wf:(g==1)?Wi:(g==2)?Wu:Wo;

        float w = W[q*512 + k];
        g_Wt[(g*256 + k)*256 + q] = w;                   // fp32 for fallback

        __half w0, w1; split2h(w, w0, w1);
        uint32_t off = (uint32_t)((q>>3)*512 + (q&7)*64 + (k&31)*2);
        off ^= (off>>3) & 0x30;                          // SW64 swizzle
        int kc8 = k >> 5;
        *(__half*)(g_Wb + ((size_t)((g*2+0)*8 + kc8))*16384 + off) = w0;
        *(__half*)(g_Wb + ((size_t)((g*2+1)*8 + kc8))*16384 + off) = w1;

        red[k] = W[q*512 + 256 + k];
        __syncthreads();
        for (int s = 128; s > 0; s >>= 1) {
            if (k < s) red[k] += red[k+s];
            __syncthreads();
        }
        if (k == 0) g_wsum[g*256 + q] = red[0];
        return;
    }

    // ---- x split + conv ----
    int row  = (blockIdx.x - 1024) * 8 + (threadIdx.x >> 5);
    int lane = threadIdx.x & 31;

    const float4* xr = (const float4*)(x + (size_t)row * D_ + lane * 8);
    float4 v0 = xr[0], v1 = xr[1];
    float e[8] = {v0.x, v0.y, v0.z, v0.w, v1.x, v1.y, v1.z, v1.w};

    // conv: prefix-parity fraction of (x > 0) over the row, in index order
    unsigned b = 0;
#pragma unroll
    for (int i = 0; i < 8; i++) b |= (e[i] > 0.0f) ? (1u << i) : 0u;
    unsigned p = b;
    p = (p ^ (p << 1)) & 0xFFu;
    p = (p ^ (p << 2)) & 0xFFu;
    p = (p ^ (p << 4)) & 0xFFu;
    unsigned lane_par = __popc(b) & 1u;
    unsigned mask = __ballot_sync(0xFFFFFFFFu, lane_par);
    unsigned pre  = __popc(mask & ((1u << lane) - 1u)) & 1u;
    int cnt = __popc((p ^ (pre ? 0xFFu : 0u)) & 0xFFu);
#pragma unroll
    for (int o = 16; o > 0; o >>= 1) cnt += __shfl_xor_sync(0xFFFFFFFFu, cnt, o);
    if (lane == 0) g_conv[row] = (float)cnt * (1.0f/256.0f);

    // exact fp16 split; 16B-contiguous pre-swizzle blocks -> single uint4 store per split
    int tile = row >> 7, r = row & 127;
    size_t base = (size_t)tile * 65536;
    uint32_t h0p[4], h1p[4];
#pragma unroll
    for (int k = 0; k < 4; k++) {
        float e0 = e[2*k], e1 = e[2*k+1];
        __half2 h0 = __floats2half2_rn(e0, e1);
        float r0 = e0 - __low2float(h0);
        float r1 = e1 - __high2float(h0);
        __half2 h1 = __floats2half2_rn(r0, r1);
        h0p[k] = *(uint32_t*)&h0;
        h1p[k] = *(uint32_t*)&h1;
    }
    uint32_t sw = sw128_tile_off(r, lane * 8);
    *(uint4*)(g_X0 + base + sw) = make_uint4(h0p[0], h0p[1], h0p[2], h0p[3]);
    *(uint4*)(g_X1 + base + sw) = make_uint4(h1p[0], h1p[1], h1p[2], h1p[3]);
}

// ============================ K1: persistent GEMM + parity ============================
__global__ __launch_bounds__(256, 1) __cluster_dims__(2, 1, 1) void qmma_kernel(
    const float* __restrict__ x,
    const float* __restrict__ bfp, const float* __restrict__ bip,
    const float* __restrict__ bup, const float* __restrict__ bop)
{
    extern __shared__ uint8_t smem_raw[];
    const int tid = threadIdx.x;
    const int ci  = blockIdx.x;
    const int iters = 6 + (ci < EXTRA ? 1 : 0);

#if USE_TCGEN05
    uint32_t sraw = smem_u32(smem_raw);
    uint32_t sb   = (sraw + 1023u) & ~1023u;
    uint8_t* sm   = smem_raw + (sb - sraw);
    const int wid = tid >> 5;
    const uint32_t rank = cluster_rank();

    if (wid == 0) TC_ALLOC(sb + SM_TPTR, 512);
    if (tid == 0) {
#pragma unroll
        for (int s = 0; s < 5; s++) { MBAR_INIT(BAR_FULL(s),1); MBAR_INIT(BAR_EMPTY(s),2); }
        MBAR_INIT(BAR_EPI,1);
        MBAR_INIT(BAR_DFREE(0),1); MBAR_INIT(BAR_DFREE(1),1);
        MBAR_INIT(BAR_X,1);
        MBAR_INIT(BAR_XFREE,1);
    }
    __syncthreads();
    uint32_t tmem;
    asm volatile("ld.shared.b32 %0, [%1];" : "=r"(tmem) : "r"(sb + SM_TPTR));

    // ---- one-time prologue: first X tile TMA; tables; arm 5 W slots ----
    if (tid == 0) {
        MBAR_EXPECT_TX(BAR_X, 131072u);
        bulk_ldn(sb + SM_A0, g_X0 + (size_t)ci * 65536, 65536u, BAR_X);
        bulk_ldn(sb + SM_A1, g_X1 + (size_t)ci * 65536, 65536u, BAR_X);
#pragma unroll
        for (int s = 0; s < 5; s++) MBAR_EXPECT_TX(BAR_FULL(s), 16384u);
    }
#pragma unroll
    for (int i = 0; i < 4; i++) {
        int idx = tid + i*256;
        int g2 = idx >> 8, q = idx & 255;
        const float* bg = (g2==0)?bfp:(g2==1)?bip:(g2==2)?bup:bop;
        ((float*)(sm + SM_THR))[idx] = 0.5f - bg[q];
        ((float*)(sm + SM_WS2))[idx] = g_wsum[idx];
    }
    __syncthreads();
    CLUSTER_ARRIVE(); CLUSTER_WAIT();

    if (wid == 2) {
        if ((tid & 31) == 0) {
            // -------- producer: X refills + W chunk stream (continuous ring) --------
            int cc = (int)rank;                   // global W chunk counter (this rank's parity)
            for (int it = 0; it < iters; it++) {
                if (it > 0) {
                    MBAR_WAIT(BAR_XFREE, (it-1)&1);
                    MBAR_EXPECT_TX(BAR_X, 131072u);
                    size_t tb = (size_t)(it*NCTA + ci) * 65536;
                    bulk_ldn(sb + SM_A0, g_X0 + tb, 65536u, BAR_X);
                    bulk_ldn(sb + SM_A1, g_X1 + tb, 65536u, BAR_X);
                }
                int lim = (it+1)*64;
                while (cc < lim) {
                    int k = cc / 5, slot = cc - k*5;
                    if (k > 0) MBAR_WAIT(BAR_EMPTY(slot), (k-1)&1);
                    int c2 = cc & 63;
                    int g = c2 >> 4, idx = c2 & 15, s = idx >> 3, kc8 = idx & 7;
                    bulk_ldn_mc(sb + SM_W + slot*16384,
                                g_Wb + ((size_t)((g*2+s)*8 + kc8))*16384,
                                16384u, BAR_FULL(slot), 0x3);
                    cc += 2;
                }
            }
        }
    } else if (wid == 0) {
        if (elect_one()) {
            // -------- MMA issuer (continuous across tiles) --------
            const uint64_t a0d = make_desc(sb + SM_A0);
            const uint64_t a1d = make_desc(sb + SM_A1);
            int sl = 0, ku = 0, dfp0 = 0, dfp1 = 0, ggc = 0, gchunk = 0;
            const int tot = 64 * iters;
            for (int it = 0; it < iters; it++) {
                MBAR_WAIT(BAR_X, it & 1);
                TC_FENCE_AFTER();
                uint32_t en = 0;
                for (int c2 = 0; c2 < 64; c2++) {
                    MBAR_WAIT(BAR_FULL(sl), ku);
                    int idx = c2 & 15, s = idx >> 3, kc8 = idx & 7;
                    if (idx == 0) {
                        if (ggc >= 2) {
                            if ((ggc & 1) == 0) { MBAR_WAIT(BAR_DFREE(0), dfp0); dfp0 ^= 1; }
                            else                { MBAR_WAIT(BAR_DFREE(1), dfp1); dfp1 ^= 1; }
                            TC_FENCE_AFTER();
                        }
                        en = 0;
                    }
                    uint32_t dT = tmem + (uint32_t)(ggc & 1) * 256;
                    uint64_t bd = make_desc64(sb + SM_W + sl*16384);
                    uint64_t aoff = (uint64_t)((kc8>>1)*1024 + (kc8&1)*4);
                    mma_ss(dT, a0d + aoff,     bd,     en); en = 1;
                    mma_ss(dT, a0d + aoff + 2, bd + 2, 1);
                    if (s == 0) {
                        mma_ss(dT, a1d + aoff,     bd,     1);
                        mma_ss(dT, a1d + aoff + 2, bd + 2, 1);
                    }
                    if (gchunk + 5 < tot) MBAR_EXPECT_TX(BAR_FULL(sl), 16384u);
                    TC_COMMIT_MC(BAR_EMPTY(sl), 0x3);
                    if (idx == 15) { TC_COMMIT(BAR_EPI); ggc++; }
                    if (++sl == 5) { sl = 0; ku ^= 1; }
                    gchunk++;
                }
                TC_COMMIT(BAR_XFREE);   // fires when this tile's MMAs complete -> A refill safe
            }
        }
    } else if (wid >= 4) {
        // -------- epilogue (continuous D ping-pong across tiles) --------
        const int row = tid - 128;
        int ep = 0;
        const int ngg = 4 * iters;
        for (int gg = 0; gg < ngg; gg++) {
            MBAR_WAIT(BAR_EPI, ep); ep ^= 1;
            TC_FENCE_AFTER();
            const int it = gg >> 2, g = gg & 3;
            const int m0 = (it*NCTA + ci) * MT;
            const float cv = g_conv[m0 + row];
            const uint32_t dT = tmem + (uint32_t)(gg & 1) * 256;
            const float* thr0 = (const float*)(sm + SM_THR) + g*256;
            const float* ws   = (const float*)(sm + SM_WS2) + g*256;
            int par = 0, cnt = 0;
            uint32_t rA[32], rB[32];
            TC_LD_X32(rA, dT);
#pragma unroll
            for (int cc = 0; cc < 8; cc += 2) {
                TC_WAIT_LD();
                TC_LD_X32(rB, dT + (cc+1)*32);
                {
                    uint32_t word = 0;
#pragma unroll
                    for (int jj = 0; jj < 32; jj++) {
                        float thr = fmaf(-cv, ws[cc*32+jj], thr0[cc*32+jj]);
                        if (__uint_as_float(rA[jj]) > thr) word |= (1u << jj);
                    }
                    uint32_t p = word;
                    p ^= p << 1; p ^= p << 2; p ^= p << 4; p ^= p << 8; p ^= p << 16;
                    cnt += __popc(p ^ (par ? 0xFFFFFFFFu : 0u));
                    par ^= (int)(p >> 31);
                }
                TC_WAIT_LD();
                if (cc + 2 < 8) TC_LD_X32(rA, dT + (cc+2)*32);
                {
                    uint32_t word = 0;
#pragma unroll
                    for (int jj = 0; jj < 32; jj++) {
                        float thr = fmaf(-cv, ws[(cc+1)*32+jj], thr0[(cc+1)*32+jj]);
                        if (__uint_as_float(rB[jj]) > thr) word |= (1u << jj);
                    }
                    uint32_t p = word;
                    p ^= p << 1; p ^= p << 2; p ^= p << 4; p ^= p << 8; p ^= p << 16;
                    cnt += __popc(p ^ (par ? 0xFFFFFFFFu : 0u));
                    par ^= (int)(p >> 31);
                }
            }
            g_gf[g*M_ + m0 + row] = (float)cnt * (1.0f/256.0f);
            TC_FENCE_BEFORE();
            asm volatile("bar.sync 1, 128;" ::: "memory");
            if (tid == 128) MBAR_ARRIVE(BAR_DFREE(gg & 1));
        }
    }

    __syncthreads();
    if (tid == 0) {
#pragma unroll
        for (int s = 0; s < 5; s++) { MBAR_INVAL(BAR_FULL(s)); MBAR_INVAL(BAR_EMPTY(s)); }
        MBAR_INVAL(BAR_EPI);
        MBAR_INVAL(BAR_DFREE(0)); MBAR_INVAL(BAR_DFREE(1));
        MBAR_INVAL(BAR_X); MBAR_INVAL(BAR_XFREE);
    }
    __syncthreads();
    if (wid == 0) TC_DEALLOC(tmem, 512);
    CLUSTER_ARRIVE(); CLUSTER_WAIT();

#else  // ======================= fp32 fallback (compute_103 pass) =======================
    float* xs    = (float*)smem_raw;                 // 128 x 260
    float* ws    = (float*)(smem_raw + 133120);      // 32 x 256
    float* convs = (float*)(smem_raw + 165888);      // 128
    unsigned char* bits = smem_raw + 166400;         // 64 x 264

    for (int it = 0; it < iters; it++) {
        const int m0 = (it*NCTA + ci) * MT;
        const float4* xblk = (const float4*)(x + (size_t)m0 * D_);
#pragma unroll 4
        for (int i = 0; i < 32; i++) {
            int idx = tid + i*256;
            int r = idx >> 6, c = idx & 63;
            *(float4*)(xs + r*260 + c*4) = xblk[idx];
        }
        __syncthreads();

        if (tid < 128) {
            const float* xrow = xs + tid*260;
            int par = 0, cnt = 0;
#pragma unroll 8
            for (int q = 0; q < D_; q++) { par ^= (xrow[q] > 0.0f); cnt += par; }
            convs[tid] = (float)cnt * (1.0f/256.0f);
        }
        __syncthreads();

        const int rowg = tid >> 4;
        const int colg = tid & 15;
        const int r0   = rowg * 4;

        for (int g = 0; g < 4; g++) {
            const float* bias = (g==0)?bfp:(g==1)?bip:(g==2)?bup:bop;
            const float* wsum = g_wsum + g*256;

            for (int rh = 0; rh < 2; rh++) {
                float acc[4][16];
#pragma unroll
                for (int i = 0; i < 4; i++)
#pragma unroll
                    for (int j = 0; j < 16; j++) acc[i][j] = 0.0f;

                for (int ks = 0; ks < 8; ks++) {
                    float4* d = (float4*)ws;
                    const float4* s = (const float4*)(g_Wt + g*65536 + ks*8192);
#pragma unroll
                    for (int i = 0; i < 8; i++) d[tid + i*256] = s[tid + i*256];
                    __syncthreads();
                    const float* xk = xs + (rh*64 + r0)*260 + ks*32;
#pragma unroll 4
                    for (int kk = 0; kk < 32; kk++) {
                        float x0 = xk[0*260 + kk];
                        float x1 = xk[1*260 + kk];
                        float x2 = xk[2*260 + kk];
                        float x3 = xk[3*260 + kk];
                        const float* wk = ws + kk*256 + colg;
#pragma unroll
                        for (int j = 0; j < 16; j++) {
                            float wv = wk[j*16];
                            acc[0][j] = fmaf(x0, wv, acc[0][j]);
                            acc[1][j] = fmaf(x1, wv, acc[1][j]);
                            acc[2][j] = fmaf(x2, wv, acc[2][j]);
                            acc[3][j] = fmaf(x3, wv, acc[3][j]);
                        }
                    }
                    __syncthreads();
                }

                float cv0 = convs[rh*64 + r0 + 0];
                float cv1 = convs[rh*64 + r0 + 1];
                float cv2 = convs[rh*64 + r0 + 2];
                float cv3 = convs[rh*64 + r0 + 3];
#pragma unroll
                for (int j = 0; j < 16; j++) {
                    int q = colg + j*16;
                    float wq = wsum[q];
                    float bq = bias[q];
                    bits[(r0+0)*264 + q] = (fmaf(cv0, wq, acc[0][j] + bq) > 0.5f);
                    bits[(r0+1)*264 + q] = (fmaf(cv1, wq, acc[1][j] + bq) > 0.5f);
                    bits[(r0+2)*264 + q] = (fmaf(cv2, wq, acc[2][j] + bq) > 0.5f);
                    bits[(r0+3)*264 + q] = (fmaf(cv3, wq, acc[3][j] + bq) > 0.5f);
                }
                __syncthreads();

                if (tid < 64) {
                    const unsigned char* br = bits + tid*264;
                    int par = 0, cnt = 0;
#pragma unroll 8
                    for (int q = 0; q < Q_; q++) { par ^= br[q]; cnt += par; }
                    g_gf[g*M_ + m0 + rh*64 + tid] = (float)cnt * (1.0f/256.0f);
                }
                __syncthreads();
            }
        }
    }
#endif
}

// ============================ K2: fused scan + output broadcast (2 blocks per batch row) ============================
// blockIdx.x = b*2 + half. Both halves redundantly compute the cheap parallel scan;
// each writes half of the T-range -> 512 CTAs saturate DRAM better than 256.
__global__ __launch_bounds__(256) void scan_out_kernel(const float* __restrict__ cx0,
                                                       float4* __restrict__ out)
{
    __shared__ float wA[8], wB[8];
    __shared__ float eA[8], eB[8];
    __shared__ float shx[T_];
    __shared__ float stail[2];

    const int b    = blockIdx.x >> 1;
    const int half = blockIdx.x & 1;
    const int tid  = threadIdx.x;
    const int lane = tid & 31;
    const int wrp  = tid >> 5;

    const int t0 = tid * 2, t1 = t0 + 1;
    const int m0 = t0 * B_ + b, m1 = t1 * B_ + b;

    float a0 = 1.0f / (1.0f + expf(-g_gf[m0]));
    float i0 = 1.0f / (1.0f + expf(-g_gf[M_ + m0]));
    float u0 = tanhf(g_gf[2*M_ + m0]);
    float o0 = 1.0f / (1.0f + expf(-g_gf[3*M_ + m0]));
    float b0v = i0 * u0;

    float a1 = 1.0f / (1.0f + expf(-g_gf[m1]));
    float i1 = 1.0f / (1.0f + expf(-g_gf[M_ + m1]));
    float u1 = tanhf(g_gf[2*M_ + m1]);
    float o1 = 1.0f / (1.0f + expf(-g_gf[3*M_ + m1]));
    float b1v = i1 * u1;

    float A  = a1 * a0;
    float Bv = fmaf(a1, b0v, b1v);

#pragma unroll
    for (int off = 1; off < 32; off <<= 1) {
        float Au = __shfl_up_sync(0xFFFFFFFFu, A,  off);
        float Bu = __shfl_up_sync(0xFFFFFFFFu, Bv, off);
        if (lane >= off) { Bv = fmaf(A, Bu, Bv); A *= Au; }
    }
    if (lane == 31) { wA[wrp] = A; wB[wrp] = Bv; }
    __syncthreads();
    if (tid == 0) {
        float pA = 1.0f, pB = 0.0f;
#pragma unroll
        for (int w = 0; w < 8; w++) {
            eA[w] = pA; eB[w] = pB;
            float nA = wA[w] * pA;
            float nB = fmaf(wA[w], pB, wB[w]);
            pA = nA; pB = nB;
        }
    }
    __syncthreads();

    float FA = A * eA[wrp];
    float FB = fmaf(A, eB[wrp], Bv);
    float XA = __shfl_up_sync(0xFFFFFFFFu, FA, 1);
    float XB = __shfl_up_sync(0xFFFFFFFFu, FB, 1);
    if (lane == 0) { XA = eA[wrp]; XB = eB[wrp]; }

    float c0  = cx0[b * H_];
    float cin = fmaf(XA, c0, XB);
    float cxa = fmaf(a0, cin, b0v);
    float cxb = fmaf(a1, cxa, b1v);

    shx[t0] = o0 * tanhf(cxa);
    float hx1 = o1 * tanhf(cxb);
    shx[t1] = hx1;
    if (t1 == T_ - 1) { stail[0] = hx1; stail[1] = cxb; }
    __syncthreads();

    // this half writes t in [half*256, half*256+256): 64 iterations of 256 threads
#pragma unroll 4
    for (int i = 0; i < 64; i++) {
        int flat = i * 256 + tid;
        int t = (half << 8) + (flat >> 6);
        int c = flat & 63;
        float v = shx[t];
        __stcs(&out[((size_t)t * B_ + b) * 64 + c], make_float4(v, v, v, v));
    }
    const unsigned OUTS_F4 = (unsigned)T_ * B_ * (H_/4);
    if (half == 1 && tid < 64) {
        float v = stail[0];
        __stcs(&out[OUTS_F4 + (unsigned)b * 64 + tid], make_float4(v, v, v, v));
        float v2 = stail[1];
        __stcs(&out[OUTS_F4 + (unsigned)(B_ * (H_/4)) + (unsigned)b * 64 + tid], make_float4(v2, v2, v2, v2));
    }
}

// ============================ launch ============================
extern "C" void kernel_launch(void* const* d_in, const int* in_sizes, int n_in,
                              void* d_out, int out_size)
{
    const float* x   = (const float*)d_in[0];
    const float* cx0 = (const float*)d_in[2];
    const float* Wf  = (const float*)d_in[3];
    const float* bf_ = (const float*)d_in[4];
    const float* Wi  = (const float*)d_in[5];
    const float* bi_ = (const float*)d_in[6];
    const float* Wu  = (const float*)d_in[7];
    const float* bu_ = (const float*)d_in[8];
    const float* Wo  = (const float*)d_in[9];
    const float* bo_ = (const float*)d_in[10];

    cudaFuncSetAttribute(qmma_kernel, cudaFuncAttributeMaxDynamicSharedMemorySize, SMEM_DYN);

    prep_xsplit_kernel<<<1024 + M_/8, 256>>>(x, Wf, Wi, Wu, Wo);
    qmma_kernel<<<NCTA, 256, SMEM_DYN>>>(x, bf_, bi_, bu_, bo_);
    scan_out_kernel<<<B_*2, 256>>>(cx0, (float4*)d_out);
}

// round 17
// speedup vs baseline: 1.8083x; 1.0287x over previous
#include <cuda_runtime.h>
#include <cuda_bf16.h>
#include <cuda_fp16.h>
#include <math.h>
#include <stdint.h>

#define T_ 512
#define B_ 256
#define D_ 256
#define H_ 256
#define Q_ 256
#define M_ (T_*B_)
#define MT 128
#define NTILES (M_/MT)
#define NCTA 152
#define EXTRA (NTILES - NCTA*6)

#if defined(__CUDA_ARCH__) && (defined(__CUDA_ARCH_FEAT_SM103_ALL) || defined(__CUDA_ARCH_FEAT_SM100_ALL) || defined(__CUDA_ARCH_FEAT_SM110_ALL) || (defined(__CUDA_ARCH_SPECIFIC__) && (__CUDA_ARCH_SPECIFIC__ == 1030 || __CUDA_ARCH_SPECIFIC__ == 1000)))
#define USE_TCGEN05 1
#else
#define USE_TCGEN05 0
#endif

#define IDESC ((1u<<4)|((256u/8)<<17)|((128u/16)<<24))

// ---- scratch ----
__device__ float g_wsum[4*256];
__device__ float g_Wt[4*256*256];                        // fp32 (fallback path)
__device__ float g_gf[4*M_];
__device__ float g_conv[M_];
__device__ __align__(1024) uint8_t g_Wb[4*2*8*16384];    // [gate][split][kc8] 16KB SW64 fp16 chunks
__device__ __align__(1024) uint8_t g_X0[(size_t)M_*D_*2]; // pre-split x0, SW128 64KB tiles
__device__ __align__(1024) uint8_t g_X1[(size_t)M_*D_*2]; // pre-split x1, SW128 64KB tiles

// ---- smem offsets ----
#define SM_A0     0                      // 65536 : x0 SW128 tile
#define SM_A1     65536                  // 65536 : x1 SW128 tile
#define SM_W      131072                 // 5 x 16384 weight ring
#define SM_THR    213504                 // 4*256 floats (0.5 - bias)
#define SM_WS2    217600                 // 4*256 floats (wsum)
#define SM_TPTR   221696
#define SM_BAR    221712
#define SMEM_DYN  223232

#define BAR_FULL(s)  (sb + SM_BAR + (s)*8)        // 5 slots
#define BAR_EMPTY(s) (sb + SM_BAR + 40 + (s)*8)   // 5 slots
#define BAR_EPI      (sb + SM_BAR + 80)
#define BAR_DFREE(b) (sb + SM_BAR + 88 + (b)*8)   // 2 buffers
#define BAR_X        (sb + SM_BAR + 104)
#define BAR_XFREE    (sb + SM_BAR + 112)

// ============================ common helpers ============================
__device__ __forceinline__ uint32_t smem_u32(const void* p){
    uint32_t a;
    asm("{ .reg .u64 t; cvta.to.shared.u64 t, %1; cvt.u32.u64 %0, t; }" : "=r"(a) : "l"(p));
    return a;
}
__device__ __forceinline__ void split2h(float v, __half& s0, __half& s1){
    s0 = __float2half_rn(v);
    s1 = __float2half_rn(v - __half2float(s0));
}
__device__ __forceinline__ uint32_t sw128_tile_off(int r, int c){
    uint32_t off = (uint32_t)(((r>>3) + (c>>6)*16)*1024 + (r&7)*128 + (c&63)*2);
    return off ^ ((off>>3) & 0x70);
}

#if USE_TCGEN05
// ============================ tcgen05 PTX helpers ============================
__device__ __forceinline__ uint32_t elect_one(){
    uint32_t p;
    asm volatile("{\n\t.reg .pred p;\n\telect.sync _|p, 0xFFFFFFFF;\n\tselp.b32 %0,1,0,p;\n\t}":"=r"(p));
    return p;
}
__device__ __forceinline__ uint32_t cluster_rank(){
    uint32_t r; asm("mov.u32 %0, %%cluster_ctarank;" : "=r"(r)); return r;
}
#define MBAR_INIT(a,c) asm volatile("mbarrier.init.shared.b64 [%0], %1;"::"r"(a),"r"(c):"memory")
#define MBAR_INVAL(a)  asm volatile("mbarrier.inval.shared.b64 [%0];"::"r"(a):"memory")
#define MBAR_ARRIVE(a) asm volatile("mbarrier.arrive.shared.b64 _, [%0];"::"r"(a):"memory")
#define MBAR_WAIT(a,ph) do{ uint32_t _m=(a),_p=(ph),_d; \
    asm volatile("{\n\t.reg .pred p;\n\tmbarrier.try_wait.parity.acquire.cta.shared::cta.b64 p,[%1],%2;\n\tselp.b32 %0,1,0,p;\n\t}":"=r"(_d):"r"(_m),"r"(_p):"memory"); \
    if(!_d){ asm volatile("{\n\t.reg .pred P1;\n\tWL_%=:\n\tmbarrier.try_wait.parity.acquire.cta.shared::cta.b64 P1,[%0],%1,0x989680;\n\t@P1 bra.uni WD_%=;\n\tbra.uni WL_%=;\n\tWD_%=:\n\t}"::"r"(_m),"r"(_p):"memory"); } }while(0)
#define MBAR_EXPECT_TX(a,n) asm volatile("mbarrier.arrive.expect_tx.shared.b64 _, [%0], %1;"::"r"(a),"r"(n):"memory")

#define TC_ALLOC(sa,n)   asm volatile("tcgen05.alloc.cta_group::1.sync.aligned.shared::cta.b32 [%0], %1;"::"r"(sa),"r"(n):"memory")
#define TC_DEALLOC(t,n)  asm volatile("tcgen05.dealloc.cta_group::1.sync.aligned.b32 %0, %1;"::"r"(t),"r"(n))
#define TC_COMMIT(a)     asm volatile("tcgen05.commit.cta_group::1.mbarrier::arrive::one.shared::cluster.b64 [%0];"::"r"(a):"memory")
#define TC_COMMIT_MC(a,mask) asm volatile("tcgen05.commit.cta_group::1.mbarrier::arrive::one.shared::cluster.multicast::cluster.b64 [%0], %1;"::"r"(a),"h"((uint16_t)(mask)):"memory")
#define TC_FENCE_AFTER()  asm volatile("tcgen05.fence::after_thread_sync;":::"memory")
#define TC_FENCE_BEFORE() asm volatile("tcgen05.fence::before_thread_sync;":::"memory")
#define TC_WAIT_LD()     asm volatile("tcgen05.wait::ld.sync.aligned;":::"memory")
#define CLUSTER_ARRIVE() asm volatile("barrier.cluster.arrive.aligned;" ::: "memory")
#define CLUSTER_WAIT()   asm volatile("barrier.cluster.wait.aligned;" ::: "memory")

#define TC_LD_X32(r, a) \
    asm volatile("tcgen05.ld.sync.aligned.32x32b.x32.b32 " \
        "{%0,%1,%2,%3,%4,%5,%6,%7,%8,%9,%10,%11,%12,%13,%14,%15," \
        "%16,%17,%18,%19,%20,%21,%22,%23,%24,%25,%26,%27,%28,%29,%30,%31}, [%32];" \
        : "=r"((r)[0]),"=r"((r)[1]),"=r"((r)[2]),"=r"((r)[3]),"=r"((r)[4]),"=r"((r)[5]),"=r"((r)[6]),"=r"((r)[7]), \
          "=r"((r)[8]),"=r"((r)[9]),"=r"((r)[10]),"=r"((r)[11]),"=r"((r)[12]),"=r"((r)[13]),"=r"((r)[14]),"=r"((r)[15]), \
          "=r"((r)[16]),"=r"((r)[17]),"=r"((r)[18]),"=r"((r)[19]),"=r"((r)[20]),"=r"((r)[21]),"=r"((r)[22]),"=r"((r)[23]), \
          "=r"((r)[24]),"=r"((r)[25]),"=r"((r)[26]),"=r"((r)[27]),"=r"((r)[28]),"=r"((r)[29]),"=r"((r)[30]),"=r"((r)[31]) \
        : "r"(a))

static constexpr uint64_t DESC_BASE_SW128 =
    (uint64_t(2)<<61) | (uint64_t(1)<<46) | (uint64_t(64)<<32) | (uint64_t(1)<<16);
static constexpr uint64_t DESC_BASE_SW64 =
    (uint64_t(4)<<61) | (uint64_t(1)<<46) | (uint64_t(32)<<32) | (uint64_t(1)<<16);
__device__ __forceinline__ uint64_t make_desc(uint32_t addr){
    return DESC_BASE_SW128 | (uint64_t)((addr>>4)&0x3FFF);
}
__device__ __forceinline__ uint64_t make_desc64(uint32_t addr){
    return DESC_BASE_SW64 | (uint64_t)((addr>>4)&0x3FFF);
}
__device__ __forceinline__ void mma_ss(uint32_t d, uint64_t a, uint64_t b, uint32_t en){
    asm volatile("{\n\t.reg .pred p;\n\tsetp.ne.u32 p, %4, 0;\n\t"
        "tcgen05.mma.cta_group::1.kind::f16 [%0], %1, %2, %3, {%5,%5,%5,%5}, p;\n\t}"
        :: "r"(d), "l"(a), "l"(b), "r"(IDESC), "r"(en), "r"(0u) : "memory");
}
__device__ __forceinline__ void bulk_ldn(uint32_t dst, const void* src, uint32_t n, uint32_t mbar){
    asm volatile("{\n\t.reg .u64 g;\n\tcvta.to.global.u64 g, %1;\n\t"
        "cp.async.bulk.shared::cluster.global.mbarrier::complete_tx::bytes [%0], [g], %2, [%3];\n\t}"
        :: "r"(dst), "l"(src), "r"(n), "r"(mbar) : "memory");
}
__device__ __forceinline__ void bulk_ldn_mc(uint32_t dst, const void* src, uint32_t n, uint32_t mbar, uint16_t mask){
    asm volatile("{\n\t.reg .u64 g;\n\tcvta.to.global.u64 g, %1;\n\t"
        "cp.async.bulk.shared::cluster.global.mbarrier::complete_tx::bytes.multicast::cluster [%0], [g], %2, [%3], %4;\n\t}"
        :: "r"(dst), "l"(src), "r"(n), "r"(mbar), "h"(mask) : "memory");
}
#endif // USE_TCGEN05

// ============================ K0: fused weight prep + x split/conv ============================
__global__ __launch_bounds__(256) void prep_xsplit_kernel(
    const float* __restrict__ x,
    const float* __restrict__ Wf, const float* __restrict__ Wi,
    const float* __restrict__ Wu, const float* __restrict__ Wo)
{
    __shared__ float red[256];

    if (blockIdx.x < 1024) {
        // ---- weight prep: SW64 16KB chunks [gate][split][kc8] (256 q x 32 k) ----
        int g = blockIdx.x >> 8;
        int q = blockIdx.x & 255;
        int k = threadIdx.x;
        const float* W = (g==0)?Wf:(g==1)?Wi:(g==2)?Wu:Wo;

        float w = W[q*512 + k];
        g_Wt[(g*256 + k)*256 + q] = w;                   // fp32 for fallback

        __half w0, w1; split2h(w, w0, w1);
        uint32_t off = (uint32_t)((q>>3)*512 + (q&7)*64 + (k&31)*2);
        off ^= (off>>3) & 0x30;                          // SW64 swizzle
        int kc8 = k >> 5;
        *(__half*)(g_Wb + ((size_t)((g*2+0)*8 + kc8))*16384 + off) = w0;
        *(__half*)(g_Wb + ((size_t)((g*2+1)*8 + kc8))*16384 + off) = w1;

        red[k] = W[q*512 + 256 + k];
        __syncthreads();
        for (int s = 128; s > 0; s >>= 1) {
            if (k < s) red[k] += red[k+s];
            __syncthreads();
        }
        if (k == 0) g_wsum[g*256 + q] = red[0];
        return;
    }

    // ---- x split + conv (REVERSE tile order: last-written tiles = first read by qmma, L2-warm) ----
    int xb   = (M_/8 - 1) - (int)(blockIdx.x - 1024);
    int row  = xb * 8 + (threadIdx.x >> 5);
    int lane = threadIdx.x & 31;

    const float4* xr = (const float4*)(x + (size_t)row * D_ + lane * 8);
    float4 v0 = xr[0], v1 = xr[1];
    float e[8] = {v0.x, v0.y, v0.z, v0.w, v1.x, v1.y, v1.z, v1.w};

    // conv: prefix-parity fraction of (x > 0) over the row, in index order
    unsigned b = 0;
#pragma unroll
    for (int i = 0; i < 8; i++) b |= (e[i] > 0.0f) ? (1u << i) : 0u;
    unsigned p = b;
    p = (p ^ (p << 1)) & 0xFFu;
    p = (p ^ (p << 2)) & 0xFFu;
    p = (p ^ (p << 4)) & 0xFFu;
    unsigned lane_par = __popc(b) & 1u;
    unsigned mask = __ballot_sync(0xFFFFFFFFu, lane_par);
    unsigned pre  = __popc(mask & ((1u << lane) - 1u)) & 1u;
    int cnt = __popc((p ^ (pre ? 0xFFu : 0u)) & 0xFFu);
    cnt = __reduce_add_sync(0xFFFFFFFFu, cnt);
    if (lane == 0) g_conv[row] = (float)cnt * (1.0f/256.0f);

    // exact fp16 split; 16B-contiguous pre-swizzle blocks -> single uint4 store per split
    int tile = row >> 7, r = row & 127;
    size_t base = (size_t)tile * 65536;
    uint32_t h0p[4], h1p[4];
#pragma unroll
    for (int k = 0; k < 4; k++) {
        float e0 = e[2*k], e1 = e[2*k+1];
        __half2 h0 = __floats2half2_rn(e0, e1);
        float r0 = e0 - __low2float(h0);
        float r1 = e1 - __high2float(h0);
        __half2 h1 = __floats2half2_rn(r0, r1);
        h0p[k] = *(uint32_t*)&h0;
        h1p[k] = *(uint32_t*)&h1;
    }
    uint32_t sw = sw128_tile_off(r, lane * 8);
    *(uint4*)(g_X0 + base + sw) = make_uint4(h0p[0], h0p[1], h0p[2], h0p[3]);
    *(uint4*)(g_X1 + base + sw) = make_uint4(h1p[0], h1p[1], h1p[2], h1p[3]);
}

// ============================ K1: persistent GEMM + parity ============================
__global__ __launch_bounds__(256, 1) __cluster_dims__(2, 1, 1) void qmma_kernel(
    const float* __restrict__ x,
    const float* __restrict__ bfp, const float* __restrict__ bip,
    const float* __restrict__ bup, const float* __restrict__ bop)
{
    extern __shared__ uint8_t smem_raw[];
    const int tid = threadIdx.x;
    const int ci  = blockIdx.x;
    const int iters = 6 + (ci < EXTRA ? 1 : 0);

#if USE_TCGEN05
    uint32_t sraw = smem_u32(smem_raw);
    uint32_t sb   = (sraw + 1023u) & ~1023u;
    uint8_t* sm   = smem_raw + (sb - sraw);
    const int wid = tid >> 5;
    const int lane = tid & 31;
    const uint32_t rank = cluster_rank();

    if (wid == 0) TC_ALLOC(sb + SM_TPTR, 512);
    if (tid == 0) {
#pragma unroll
        for (int s = 0; s < 5; s++) { MBAR_INIT(BAR_FULL(s),1); MBAR_INIT(BAR_EMPTY(s),2); }
        MBAR_INIT(BAR_EPI,1);
        MBAR_INIT(BAR_DFREE(0),1); MBAR_INIT(BAR_DFREE(1),1);
        MBAR_INIT(BAR_X,1);
        MBAR_INIT(BAR_XFREE,1);
    }
    __syncthreads();
    uint32_t tmem;
    asm volatile("ld.shared.b32 %0, [%1];" : "=r"(tmem) : "r"(sb + SM_TPTR));

    // ---- one-time prologue: first X tile TMA; tables; arm 5 W slots ----
    if (tid == 0) {
        MBAR_EXPECT_TX(BAR_X, 131072u);
        bulk_ldn(sb + SM_A0, g_X0 + (size_t)ci * 65536, 65536u, BAR_X);
        bulk_ldn(sb + SM_A1, g_X1 + (size_t)ci * 65536, 65536u, BAR_X);
#pragma unroll
        for (int s = 0; s < 5; s++) MBAR_EXPECT_TX(BAR_FULL(s), 16384u);
    }
#pragma unroll
    for (int i = 0; i < 4; i++) {
        int idx = tid + i*256;
        int g2 = idx >> 8, q = idx & 255;
        const float* bg = (g2==0)?bfp:(g2==1)?bip:(g2==2)?bup:bop;
        ((float*)(sm + SM_THR))[idx] = 0.5f - bg[q];
        ((float*)(sm + SM_WS2))[idx] = g_wsum[idx];
    }
    __syncthreads();
    CLUSTER_ARRIVE(); CLUSTER_WAIT();

    if (wid == 2) {
        if (lane == 0) {
            // -------- W streamer: continuous ring, EMPTY-gated ONLY (never drains
            //          at tile boundaries; A refills handled by lane 1) --------
            const int tot = 64 * iters;
            for (int cc = (int)rank; cc < tot; cc += 2) {
                int k = cc / 5, slot = cc - k*5;
                if (k > 0) MBAR_WAIT(BAR_EMPTY(slot), (k-1)&1);
                int c2 = cc & 63;
                int g = c2 >> 4, idx = c2 & 15, s = idx >> 3, kc8 = idx & 7;
                bulk_ldn_mc(sb + SM_W + slot*16384,
                            g_Wb + ((size_t)((g*2+s)*8 + kc8))*16384,
                            16384u, BAR_FULL(slot), 0x3);
            }
        } else if (lane == 1) {
            // -------- A refiller: XFREE-gated only --------
            for (int it = 1; it < iters; it++) {
                MBAR_WAIT(BAR_XFREE, (it-1)&1);
                MBAR_EXPECT_TX(BAR_X, 131072u);
                size_t tb = (size_t)(it*NCTA + ci) * 65536;
                bulk_ldn(sb + SM_A0, g_X0 + tb, 65536u, BAR_X);
                bulk_ldn(sb + SM_A1, g_X1 + tb, 65536u, BAR_X);
            }
        }
    } else if (wid == 0) {
        if (elect_one()) {
            // -------- MMA issuer (continuous across tiles) --------
            const uint64_t a0d = make_desc(sb + SM_A0);
            const uint64_t a1d = make_desc(sb + SM_A1);
            int sl = 0, ku = 0, dfp0 = 0, dfp1 = 0, ggc = 0, gchunk = 0;
            const int tot = 64 * iters;
            for (int it = 0; it < iters; it++) {
                MBAR_WAIT(BAR_X, it & 1);
                TC_FENCE_AFTER();
                uint32_t en = 0;
                for (int c2 = 0; c2 < 64; c2++) {
                    MBAR_WAIT(BAR_FULL(sl), ku);
                    int idx = c2 & 15, s = idx >> 3, kc8 = idx & 7;
                    if (idx == 0) {
                        if (ggc >= 2) {
                            if ((ggc & 1) == 0) { MBAR_WAIT(BAR_DFREE(0), dfp0); dfp0 ^= 1; }
                            else                { MBAR_WAIT(BAR_DFREE(1), dfp1); dfp1 ^= 1; }
                            TC_FENCE_AFTER();
                        }
                        en = 0;
                    }
                    uint32_t dT = tmem + (uint32_t)(ggc & 1) * 256;
                    uint64_t bd = make_desc64(sb + SM_W + sl*16384);
                    uint64_t aoff = (uint64_t)((kc8>>1)*1024 + (kc8&1)*4);
                    mma_ss(dT, a0d + aoff,     bd,     en); en = 1;
                    mma_ss(dT, a0d + aoff + 2, bd + 2, 1);
                    if (s == 0) {
                        mma_ss(dT, a1d + aoff,     bd,     1);
                        mma_ss(dT, a1d + aoff + 2, bd + 2, 1);
                    }
                    if (gchunk + 5 < tot) MBAR_EXPECT_TX(BAR_FULL(sl), 16384u);
                    TC_COMMIT_MC(BAR_EMPTY(sl), 0x3);
                    if (idx == 15) { TC_COMMIT(BAR_EPI); ggc++; }
                    if (++sl == 5) { sl = 0; ku ^= 1; }
                    gchunk++;
                }
                TC_COMMIT(BAR_XFREE);   // fires when this tile's MMAs complete -> A refill safe
            }
        }
    } else if (wid >= 4) {
        // -------- epilogue (continuous D ping-pong across tiles) --------
        const int row = tid - 128;
        int ep = 0;
        const int ngg = 4 * iters;
        for (int gg = 0; gg < ngg; gg++) {
            MBAR_WAIT(BAR_EPI, ep); ep ^= 1;
            TC_FENCE_AFTER();
            const int it = gg >> 2, g = gg & 3;
            const int m0 = (it*NCTA + ci) * MT;
            const float cv = g_conv[m0 + row];
            const uint32_t dT = tmem + (uint32_t)(gg & 1) * 256;
            const float* thr0 = (const float*)(sm + SM_THR) + g*256;
            const float* ws   = (const float*)(sm + SM_WS2) + g*256;
            int par = 0, cnt = 0;
            uint32_t rA[32], rB[32];
            TC_LD_X32(rA, dT);
#pragma unroll
            for (int cc = 0; cc < 8; cc += 2) {
                TC_WAIT_LD();
                TC_LD_X32(rB, dT + (cc+1)*32);
                {
                    uint32_t word = 0;
#pragma unroll
                    for (int jj = 0; jj < 32; jj++) {
                        float thr = fmaf(-cv, ws[cc*32+jj], thr0[cc*32+jj]);
                        if (__uint_as_float(rA[jj]) > thr) word |= (1u << jj);
                    }
                    uint32_t p = word;
                    p ^= p << 1; p ^= p << 2; p ^= p << 4; p ^= p << 8; p ^= p << 16;
                    cnt += __popc(p ^ (par ? 0xFFFFFFFFu : 0u));
                    par ^= (int)(p >> 31);
                }
                TC_WAIT_LD();
                if (cc + 2 < 8) TC_LD_X32(rA, dT + (cc+2)*32);
                {
                    uint32_t word = 0;
#pragma unroll
                    for (int jj = 0; jj < 32; jj++) {
                        float thr = fmaf(-cv, ws[(cc+1)*32+jj], thr0[(cc+1)*32+jj]);
                        if (__uint_as_float(rB[jj]) > thr) word |= (1u << jj);
                    }
                    uint32_t p = word;
                    p ^= p << 1; p ^= p << 2; p ^= p << 4; p ^= p << 8; p ^= p << 16;
                    cnt += __popc(p ^ (par ? 0xFFFFFFFFu : 0u));
                    par ^= (int)(p >> 31);
                }
            }
            g_gf[g*M_ + m0 + row] = (float)cnt * (1.0f/256.0f);
            TC_FENCE_BEFORE();
            asm volatile("bar.sync 1, 128;" ::: "memory");
            if (tid == 128) MBAR_ARRIVE(BAR_DFREE(gg & 1));
        }
    }

    __syncthreads();
    if (tid == 0) {
#pragma unroll
        for (int s = 0; s < 5; s++) { MBAR_INVAL(BAR_FULL(s)); MBAR_INVAL(BAR_EMPTY(s)); }
        MBAR_INVAL(BAR_EPI);
        MBAR_INVAL(BAR_DFREE(0)); MBAR_INVAL(BAR_DFREE(1));
        MBAR_INVAL(BAR_X); MBAR_INVAL(BAR_XFREE);
    }
    __syncthreads();
    if (wid == 0) TC_DEALLOC(tmem, 512);
    CLUSTER_ARRIVE(); CLUSTER_WAIT();

#else  // ======================= fp32 fallback (compute_103 pass) =======================
    float* xs    = (float*)smem_raw;                 // 128 x 260
    float* ws    = (float*)(smem_raw + 133120);      // 32 x 256
    float* convs = (float*)(smem_raw + 165888);      // 128
    unsigned char* bits = smem_raw + 166400;         // 64 x 264

    for (int it = 0; it < iters; it++) {
        const int m0 = (it*NCTA + ci) * MT;
        const float4* xblk = (const float4*)(x + (size_t)m0 * D_);
#pragma unroll 4
        for (int i = 0; i < 32; i++) {
            int idx = tid + i*256;
            int r = idx >> 6, c = idx & 63;
            *(float4*)(xs + r*260 + c*4) = xblk[idx];
        }
        __syncthreads();

        if (tid < 128) {
            const float* xrow = xs + tid*260;
            int par = 0, cnt = 0;
#pragma unroll 8
            for (int q = 0; q < D_; q++) { par ^= (xrow[q] > 0.0f); cnt += par; }
            convs[tid] = (float)cnt * (1.0f/256.0f);
        }
        __syncthreads();

        const int rowg = tid >> 4;
        const int colg = tid & 15;
        const int r0   = rowg * 4;

        for (int g = 0; g < 4; g++) {
            const float* bias = (g==0)?bfp:(g==1)?bip:(g==2)?bup:bop;
            const float* wsum = g_wsum + g*256;

            for (int rh = 0; rh < 2; rh++) {
                float acc[4][16];
#pragma unroll
                for (int i = 0; i < 4; i++)
#pragma unroll
                    for (int j = 0; j < 16; j++) acc[i][j] = 0.0f;

                for (int ks = 0; ks < 8; ks++) {
                    float4* d = (float4*)ws;
                    const float4* s = (const float4*)(g_Wt + g*65536 + ks*8192);
#pragma unroll
                    for (int i = 0; i < 8; i++) d[tid + i*256] = s[tid + i*256];
                    __syncthreads();
                    const float* xk = xs + (rh*64 + r0)*260 + ks*32;
#pragma unroll 4
                    for (int kk = 0; kk < 32; kk++) {
                        float x0 = xk[0*260 + kk];
                        float x1 = xk[1*260 + kk];
                        float x2 = xk[2*260 + kk];
                        float x3 = xk[3*260 + kk];
                        const float* wk = ws + kk*256 + colg;
#pragma unroll
                        for (int j = 0; j < 16; j++) {
                            float wv = wk[j*16];
                            acc[0][j] = fmaf(x0, wv, acc[0][j]);
                            acc[1][j] = fmaf(x1, wv, acc[1][j]);
                            acc[2][j] = fmaf(x2, wv, acc[2][j]);
                            acc[3][j] = fmaf(x3, wv, acc[3][j]);
                        }
                    }
                    __syncthreads();
                }

                float cv0 = convs[rh*64 + r0 + 0];
                float cv1 = convs[rh*64 + r0 + 1];
                float cv2 = convs[rh*64 + r0 + 2];
                float cv3 = convs[rh*64 + r0 + 3];
#pragma unroll
                for (int j = 0; j < 16; j++) {
                    int q = colg + j*16;
                    float wq = wsum[q];
                    float bq = bias[q];
                    bits[(r0+0)*264 + q] = (fmaf(cv0, wq, acc[0][j] + bq) > 0.5f);
                    bits[(r0+1)*264 + q] = (fmaf(cv1, wq, acc[1][j] + bq) > 0.5f);
                    bits[(r0+2)*264 + q] = (fmaf(cv2, wq, acc[2][j] + bq) > 0.5f);
                    bits[(r0+3)*264 + q] = (fmaf(cv3, wq, acc[3][j] + bq) > 0.5f);
                }
                __syncthreads();

                if (tid < 64) {
                    const unsigned char* br = bits + tid*264;
                    int par = 0, cnt = 0;
#pragma unroll 8
                    for (int q = 0; q < Q_; q++) { par ^= br[q]; cnt += par; }
                    g_gf[g*M_ + m0 + rh*64 + tid] = (float)cnt * (1.0f/256.0f);
                }
                __syncthreads();
            }
        }
    }
#endif
}

// ============================ K2: fused scan + output broadcast ============================
__global__ __launch_bounds__(256) void scan_out_kernel(const float* __restrict__ cx0,
                                                       float4* __restrict__ out)
{
    __shared__ float wA[8], wB[8];
    __shared__ float eA[8], eB[8];
    __shared__ float shx[T_];
    __shared__ float stail[2];

    const int b    = blockIdx.x;
    const int tid  = threadIdx.x;
    const int lane = tid & 31;
    const int wrp  = tid >> 5;

    const int t0 = tid * 2, t1 = t0 + 1;
    const int m0 = t0 * B_ + b, m1 = t1 * B_ + b;

    float a0 = 1.0f / (1.0f + expf(-g_gf[m0]));
    float i0 = 1.0f / (1.0f + expf(-g_gf[M_ + m0]));
    float u0 = tanhf(g_gf[2*M_ + m0]);
    float o0 = 1.0f / (1.0f + expf(-g_gf[3*M_ + m0]));
    float b0v = i0 * u0;

    float a1 = 1.0f / (1.0f + expf(-g_gf[m1]));
    float i1 = 1.0f / (1.0f + expf(-g_gf[M_ + m1]));
    float u1 = tanhf(g_gf[2*M_ + m1]);
    float o1 = 1.0f / (1.0f + expf(-g_gf[3*M_ + m1]));
    float b1v = i1 * u1;

    float A  = a1 * a0;
    float Bv = fmaf(a1, b0v, b1v);

#pragma unroll
    for (int off = 1; off < 32; off <<= 1) {
        float Au = __shfl_up_sync(0xFFFFFFFFu, A,  off);
        float Bu = __shfl_up_sync(0xFFFFFFFFu, Bv, off);
        if (lane >= off) { Bv = fmaf(A, Bu, Bv); A *= Au; }
    }
    if (lane == 31) { wA[wrp] = A; wB[wrp] = Bv; }
    __syncthreads();
    if (tid == 0) {
        float pA = 1.0f, pB = 0.0f;
#pragma unroll
        for (int w = 0; w < 8; w++) {
            eA[w] = pA; eB[w] = pB;
            float nA = wA[w] * pA;
            float nB = fmaf(wA[w], pB, wB[w]);
            pA = nA; pB = nB;
        }
    }
    __syncthreads();

    float FA = A * eA[wrp];
    float FB = fmaf(A, eB[wrp], Bv);
    float XA = __shfl_up_sync(0xFFFFFFFFu, FA, 1);
    float XB = __shfl_up_sync(0xFFFFFFFFu, FB, 1);
    if (lane == 0) { XA = eA[wrp]; XB = eB[wrp]; }

    float c0  = cx0[b * H_];
    float cin = fmaf(XA, c0, XB);
    float cxa = fmaf(a0, cin, b0v);
    float cxb = fmaf(a1, cxa, b1v);

    shx[t0] = o0 * tanhf(cxa);
    float hx1 = o1 * tanhf(cxb);
    shx[t1] = hx1;
    if (t1 == T_ - 1) { stail[0] = hx1; stail[1] = cxb; }
    __syncthreads();

#pragma unroll 4
    for (int i = 0; i < 128; i++) {
        int flat = i * 256 + tid;
        int t = flat >> 6, c = flat & 63;
        float v = shx[t];
        __stcs(&out[((size_t)t * B_ + b) * 64 + c], make_float4(v, v, v, v));
    }
    const unsigned OUTS_F4 = (unsigned)T_ * B_ * (H_/4);
    if (tid < 64) {
        float v = stail[0];
        __stcs(&out[OUTS_F4 + (unsigned)b * 64 + tid], make_float4(v, v, v, v));
        float v2 = stail[1];
        __stcs(&out[OUTS_F4 + (unsigned)(B_ * (H_/4)) + (unsigned)b * 64 + tid], make_float4(v2, v2, v2, v2));
    }
}

// ============================ launch ============================
extern "C" void kernel_launch(void* const* d_in, const int* in_sizes, int n_in,
                              void* d_out, int out_size)
{
    const float* x   = (const float*)d_in[0];
    const float* cx0 = (const float*)d_in[2];
    const float* Wf  = (const float*)d_in[3];
    const float* bf_ = (const float*)d_in[4];
    const float* Wi  = (const float*)d_in[5];
    const float* bi_ = (const float*)d_in[6];
    const float* Wu  = (const float*)d_in[7];
    const float* bu_ = (const float*)d_in[8];
    const float* Wo  = (const float*)d_in[9];
    const float* bo_ = (const float*)d_in[10];

    cudaFuncSetAttribute(qmma_kernel, cudaFuncAttributeMaxDynamicSharedMemorySize, SMEM_DYN);

    prep_xsplit_kernel<<<1024 + M_/8, 256>>>(x, Wf, Wi, Wu, Wo);
    qmma_kernel<<<NCTA, 256, SMEM_DYN>>>(x, bf_, bi_, bu_, bo_);
    scan_out_kernel<<<B_, 256>>>(cx0, (float4*)d_out);
}